// round 14
// baseline (speedup 1.0000x reference)
#include <cuda_runtime.h>
#include <cuda_fp16.h>
#include <stdint.h>
#include <math.h>

#define Dq 256
#define Mq 512
#define RB 64
#define NT 512
#define NROWS (32*4096)

// ---- SMEM layout ----
#define R_OFF  0
#define RP     2064
#define RLO    1040
#define X_OFF  132096
#define XP     1040
#define XLO    528
// Staging: 2 buffers x 16KB (k32: hi @ +0, lo @ +8192). Phase E k64 hi-only 128B pitch.
// Same 32KB region doubles as the k-split pair-reduction scratch between passes.
#define ST_OFF 198656
#define SMEM_BYTES 231424

__device__ __align__(16) __half g_memB_h[Mq*Dq], g_memB_l[Mq*Dq]; // [m][k]
__device__ __align__(16) __half g_memT_h[Dq*Mq], g_memT_l[Dq*Mq]; // [d][m]
__device__ __align__(16) __half g_wg_h[Dq*Mq],   g_wg_l[Dq*Mq];   // [e][dc]

__device__ __forceinline__ uint32_t smem_u32(const void* p){
    uint32_t a;
    asm("{ .reg .u64 t; cvta.to.shared.u64 t, %1; cvt.u32.u64 %0, t; }" : "=r"(a) : "l"(p));
    return a;
}
__device__ __forceinline__ void split_fp(float v, __half& h, __half& l){
    h = __float2half_rn(v);
    l = __float2half_rn(v - __half2float(h));
}
__device__ __forceinline__ uint32_t pk2(__half a, __half b){
    uint16_t ua = *(uint16_t*)&a, ub = *(uint16_t*)&b;
    return (uint32_t)ua | ((uint32_t)ub << 16);
}
__device__ __forceinline__ float hf2sum(uint32_t h, uint32_t l, int hi){
    uint16_t uh = hi ? (uint16_t)(h >> 16) : (uint16_t)h;
    uint16_t ul = hi ? (uint16_t)(l >> 16) : (uint16_t)l;
    __half bh = *(__half*)&uh, bl = *(__half*)&ul;
    return __half2float(bh) + __half2float(bl);
}
__device__ __forceinline__ void ldsm4(unsigned* a, uint32_t addr){
    asm volatile("ldmatrix.sync.aligned.m8n8.x4.shared.b16 {%0,%1,%2,%3}, [%4];"
        : "=r"(a[0]), "=r"(a[1]), "=r"(a[2]), "=r"(a[3]) : "r"(addr));
}
__device__ __forceinline__ void ldsm2(unsigned* b, uint32_t addr){
    asm volatile("ldmatrix.sync.aligned.m8n8.x2.shared.b16 {%0,%1}, [%2];"
        : "=r"(b[0]), "=r"(b[1]) : "r"(addr));
}
__device__ __forceinline__ void mma(float* d, const unsigned* a, const unsigned* b){
    asm volatile("mma.sync.aligned.m16n8k16.row.col.f32.f16.f16.f32 "
        "{%0,%1,%2,%3}, {%4,%5,%6,%7}, {%8,%9}, {%0,%1,%2,%3};"
        : "+f"(d[0]), "+f"(d[1]), "+f"(d[2]), "+f"(d[3])
        : "r"(a[0]), "r"(a[1]), "r"(a[2]), "r"(a[3]), "r"(b[0]), "r"(b[1]));
}
__device__ __forceinline__ void cpa16(uint32_t s, const void* g){
    asm volatile("cp.async.cg.shared.global [%0], [%1], 16;" :: "r"(s), "l"(g));
}
#define CP_COMMIT() asm volatile("cp.async.commit_group;" ::: "memory")
template<int N> __device__ __forceinline__ void cp_wait(){
    asm volatile("cp.async.wait_group %0;" :: "n"(N) : "memory");
}

// stage [128 rows][32 k] hi+lo into swizzled 64B-pitch buffer
__device__ __forceinline__ void stage2(uint32_t st, const __half* gh,
        const __half* gl, int row0, int gs, int col0){
    int idx = threadIdx.x;
    int row = idx >> 2, c = idx & 3;
    uint32_t sa = st + row*64 + ((c ^ ((row>>1)&3)) & 3)*16;
    size_t go = (size_t)(row0 + row)*gs + col0 + c*8;
    cpa16(sa, gh + go);
    cpa16(sa + 8192, gl + go);
}
// stage [128 rows][64 k] hi-only into 128B-pitch row-XOR swizzled buffer
__device__ __forceinline__ void stage1_64(uint32_t st, const __half* gh,
        int row0, int gs, int col0){
    #pragma unroll
    for (int p = 0; p < 2; p++){
        int idx = threadIdx.x + p*NT;
        int row = idx >> 3, c = idx & 7;
        uint32_t sa = st + row*128 + ((c ^ (row & 7)) & 7)*16;
        cpa16(sa, gh + (size_t)(row0 + row)*gs + col0 + c*8);
    }
}

// k-split GEMM chunk: warp computes m32 x n32 x k16 (its kw-half of a k32 chunk).
// 4 ldsm4 + 8 ldsm2 + 24 mma.
__device__ __forceinline__ void gemm_ks(float acc[2][4][4], uint32_t a0, uint32_t a1,
        uint32_t alo, uint32_t st, uint32_t bRB, uint32_t sw_ks){
    unsigned ah0[4], al0[4], ah1[4], al1[4];
    ldsm4(ah0, a0); ldsm4(al0, a0 + alo);
    ldsm4(ah1, a1); ldsm4(al1, a1 + alo);
    #pragma unroll
    for (int nb = 0; nb < 4; nb++){
        unsigned bh[2], bl[2];
        uint32_t ba = st + bRB + nb*512 + sw_ks;
        ldsm2(bh, ba); ldsm2(bl, ba + 8192);
        mma(acc[0][nb], ah0, bh); mma(acc[1][nb], ah1, bh);
        mma(acc[0][nb], ah0, bl); mma(acc[1][nb], ah1, bl);
        mma(acc[0][nb], al0, bh); mma(acc[1][nb], al1, bh);
    }
}
// hi-only k-split chunk over k64 staging: warp does m32 x n32 x k32 (kw-half).
__device__ __forceinline__ void gemm_hiks(float acc[2][4][4], uint32_t a0, uint32_t a1,
        uint32_t st, uint32_t rowB, uint32_t l7, uint32_t b8, uint32_t kw){
    #pragma unroll
    for (int ki = 0; ki < 2; ki++){
        unsigned ah0[4], ah1[4];
        ldsm4(ah0, a0 + ki*32); ldsm4(ah1, a1 + ki*32);
        uint32_t c = kw*4 + (uint32_t)ki*2 + b8;
        uint32_t sw = ((c ^ l7) & 7)*16;
        #pragma unroll
        for (int nb = 0; nb < 4; nb++){
            unsigned bh[2];
            ldsm2(bh, st + rowB + nb*1024 + sw);
            mma(acc[0][nb], ah0, bh); mma(acc[1][nb], ah1, bh);
        }
    }
}

__global__ void vm_prep(const float* __restrict__ mem, const float* __restrict__ wg){
    int idx = blockIdx.x*blockDim.x + threadIdx.x;
    if (idx < Mq*Dq){
        int m = idx >> 8, k = idx & 255;
        __half h, l;
        split_fp(mem[idx], h, l);
        g_memB_h[idx] = h;          g_memB_l[idx] = l;
        g_memT_h[k*Mq + m] = h;     g_memT_l[k*Mq + m] = l;
        split_fp(wg[idx], h, l);
        g_wg_h[idx] = h;            g_wg_l[idx] = l;
    }
}

__global__ __launch_bounds__(NT, 1)
void vm_fused(const float* __restrict__ x,
              const float* __restrict__ bg,
              float* __restrict__ out_enh,
              float* __restrict__ out_w)
{
    extern __shared__ char sm[];
    const uint32_t sm32 = smem_u32(sm);
    const uint32_t ST0 = sm32 + ST_OFF, ST1 = ST0 + 16384;
    float* red = (float*)(sm + ST_OFF);           // pair-reduction scratch (32KB)

    const int tid = threadIdx.x;
    const int wid = tid >> 5, lane = tid & 31;
    const int kw = wid & 1;                       // k-half
    const int pr = wid >> 1;                      // pair id 0..7
    const int nw = pr & 3, mw = pr >> 2;          // n-group (x32), m-half (x32)
    const int rowbase = blockIdx.x * RB;

    const uint32_t aX0 = sm32 + X_OFF + (mw*32 + (lane&15))*XP + (lane>>4)*16;
    const uint32_t aX1 = aX0 + 16*XP;
    const uint32_t aR0 = sm32 + R_OFF + (mw*32 + (lane&15))*RP + (lane>>4)*16;
    const uint32_t aR1 = aR0 + 16*RP;
    // staging lane constants
    const uint32_t bRB  = (uint32_t)(nw*32 + (lane&7))*64;
    const uint32_t t_sw = (uint32_t)(((lane&7) >> 1) & 3);
    const uint32_t b8   = (uint32_t)((lane>>3) & 1);
    const uint32_t sw_ks = (((2u*(uint32_t)kw + b8) ^ t_sw) & 3)*16;
    const uint32_t rowB64 = (uint32_t)(nw*32 + (lane&7))*128;
    const uint32_t l7 = (uint32_t)(lane & 7);
    const uint32_t kwo32 = (uint32_t)kw*32, kwo64 = (uint32_t)kw*64;
    const uint32_t redi = (uint32_t)(pr*32 + lane);

    // ---------------- Phase A: x -> split fp16 in X region -----------------
    #pragma unroll
    for (int p = 0; p < 8; p++){
        int idx = tid + p*NT;
        int r = idx >> 6, c4 = idx & 63;
        float4 v = *(const float4*)(x + (size_t)(rowbase + r)*Dq + c4*4);
        __half h0,l0,h1,l1,h2,l2,h3,l3;
        split_fp(v.x,h0,l0); split_fp(v.y,h1,l1); split_fp(v.z,h2,l2); split_fp(v.w,h3,l3);
        *(uint2*)(sm + X_OFF + r*XP + c4*8)       = make_uint2(pk2(h0,h1), pk2(h2,h3));
        *(uint2*)(sm + X_OFF + r*XP + XLO + c4*8) = make_uint2(pk2(l0,l1), pk2(l2,l3));
    }

    // ---------------- Phase B: logits = x @ memory^T ------------------------
    for (int nc = 0; nc < 4; nc++){
        float acc[2][4][4] = {};
        __syncthreads();                 // reduction scratch / staging free
        stage2(ST0, g_memB_h, g_memB_l, nc*128, Dq, 0); CP_COMMIT();
        #pragma unroll 1
        for (int kc = 0; kc < 8; kc++){
            cp_wait<0>();
            __syncthreads();
            if (kc < 7){
                stage2(((kc+1)&1)?ST1:ST0, g_memB_h, g_memB_l, nc*128, Dq, (kc+1)*32);
                CP_COMMIT();
            }
            gemm_ks(acc, aX0 + kc*64 + kwo32, aX1 + kc*64 + kwo32, XLO,
                    (kc&1)?ST1:ST0, bRB, sw_ks);
        }
        __syncthreads();
        // pair reduction kw=1 -> kw=0
        float* a = (float*)acc;
        if (kw){
            #pragma unroll
            for (int r = 0; r < 32; r++) red[r*256 + redi] = a[r];
        }
        __syncthreads();
        if (!kw){
            #pragma unroll
            for (int r = 0; r < 32; r++) a[r] += red[r*256 + redi];
            #pragma unroll
            for (int mt = 0; mt < 2; mt++)
                #pragma unroll
                for (int nb = 0; nb < 4; nb++){
                    int r = mw*32 + mt*16 + (lane>>2);
                    int c = nc*128 + nw*32 + nb*8 + 2*(lane&3);
                    *(float2*)(sm + R_OFF + r*RP + c*4)     = make_float2(acc[mt][nb][0], acc[mt][nb][1]);
                    *(float2*)(sm + R_OFF + (r+8)*RP + c*4) = make_float2(acc[mt][nb][2], acc[mt][nb][3]);
                }
        }
    }
    __syncthreads();

    // ---------------- Phase C: softmax + out_w + in-place split ------------
    for (int t4 = 0; t4 < 4; t4++){
        int r = wid*4 + t4;
        char* rbase = sm + R_OFF + r*RP;
        float v[16];
        #pragma unroll
        for (int j = 0; j < 8; j++){
            float2 p = *(float2*)(rbase + (2*lane + 64*j)*4);
            v[2*j] = p.x; v[2*j+1] = p.y;
        }
        float mx = v[0];
        #pragma unroll
        for (int i = 1; i < 16; i++) mx = fmaxf(mx, v[i]);
        #pragma unroll
        for (int o = 16; o > 0; o >>= 1) mx = fmaxf(mx, __shfl_xor_sync(~0u, mx, o));
        float s = 0.f;
        #pragma unroll
        for (int i = 0; i < 16; i++){ v[i] = __expf(v[i] - mx); s += v[i]; }
        #pragma unroll
        for (int o = 16; o > 0; o >>= 1) s += __shfl_xor_sync(~0u, s, o);
        float inv = 1.f / s;
        float* wout = out_w + (size_t)(rowbase + r)*Mq;
        #pragma unroll
        for (int j = 0; j < 8; j++){
            float w0 = v[2*j]*inv, w1 = v[2*j+1]*inv;
            v[2*j] = w0; v[2*j+1] = w1;
            *(float2*)(wout + 2*lane + 64*j) = make_float2(w0, w1);
        }
        __syncwarp();
        #pragma unroll
        for (int j = 0; j < 8; j++){
            __half h0,l0,h1,l1;
            split_fp(v[2*j], h0, l0); split_fp(v[2*j+1], h1, l1);
            int c = 2*lane + 64*j;
            *(uint32_t*)(rbase + 2*c)       = pk2(h0, h1);
            *(uint32_t*)(rbase + RLO + 2*c) = pk2(l0, l1);
        }
    }
    __syncthreads();

    // ---------------- Phase D: mr = w @ memory ------------------------------
    float dacc[2][2][4][4] = {};
    for (int nc = 0; nc < 2; nc++){
        stage2(ST0, g_memT_h, g_memT_l, nc*128, Mq, 0); CP_COMMIT();
        #pragma unroll 1
        for (int kc = 0; kc < 16; kc++){
            cp_wait<0>();
            __syncthreads();
            if (kc < 15){
                stage2(((kc+1)&1)?ST1:ST0, g_memT_h, g_memT_l, nc*128, Mq, (kc+1)*32);
                CP_COMMIT();
            }
            gemm_ks(dacc[nc], aR0 + kc*64 + kwo32, aR1 + kc*64 + kwo32, RLO,
                    (kc&1)?ST1:ST0, bRB, sw_ks);
        }
        __syncthreads();   // buffer reuse across nc passes
    }
    // pair reduction (two 32-float steps), then kw=0 stores mr split into R
    {
        float* d0 = (float*)dacc[0];
        float* d1 = (float*)dacc[1];
        if (kw){
            #pragma unroll
            for (int r = 0; r < 32; r++) red[r*256 + redi] = d0[r];
        }
        __syncthreads();
        if (!kw){
            #pragma unroll
            for (int r = 0; r < 32; r++) d0[r] += red[r*256 + redi];
        }
        __syncthreads();
        if (kw){
            #pragma unroll
            for (int r = 0; r < 32; r++) red[r*256 + redi] = d1[r];
        }
        __syncthreads();
        if (!kw){
            #pragma unroll
            for (int r = 0; r < 32; r++) d1[r] += red[r*256 + redi];
            #pragma unroll
            for (int nc = 0; nc < 2; nc++)
                #pragma unroll
                for (int mt = 0; mt < 2; mt++)
                    #pragma unroll
                    for (int nb = 0; nb < 4; nb++){
                        int r = mw*32 + mt*16 + (lane>>2);
                        int c = nc*128 + nw*32 + nb*8 + 2*(lane&3);
                        __half h0,l0,h1,l1;
                        split_fp(dacc[nc][mt][nb][0], h0, l0); split_fp(dacc[nc][mt][nb][1], h1, l1);
                        *(uint32_t*)(sm + R_OFF + r*RP + 2*c)       = pk2(h0,h1);
                        *(uint32_t*)(sm + R_OFF + r*RP + RLO + 2*c) = pk2(l0,l1);
                        split_fp(dacc[nc][mt][nb][2], h0, l0); split_fp(dacc[nc][mt][nb][3], h1, l1);
                        *(uint32_t*)(sm + R_OFF + (r+8)*RP + 2*c)       = pk2(h0,h1);
                        *(uint32_t*)(sm + R_OFF + (r+8)*RP + RLO + 2*c) = pk2(l0,l1);
                    }
        }
    }
    __syncthreads();

    // ---------------- Phase E: gate = [x ; mr] @ Wg^T (hi-only, k64) -------
    for (int nc = 0; nc < 2; nc++){
        float gacc[2][4][4] = {};
        stage1_64(ST0, g_wg_h, nc*128, Mq, 0); CP_COMMIT();
        #pragma unroll 1
        for (int kc = 0; kc < 8; kc++){
            cp_wait<0>();
            __syncthreads();
            if (kc < 7){
                stage1_64(((kc+1)&1)?ST1:ST0, g_wg_h, nc*128, Mq, (kc+1)*64);
                CP_COMMIT();
            }
            uint32_t a0 = ((kc < 4) ? (aX0 + kc*128) : (aR0 + (kc-4)*128)) + kwo64;
            uint32_t a1 = ((kc < 4) ? (aX1 + kc*128) : (aR1 + (kc-4)*128)) + kwo64;
            gemm_hiks(gacc, a0, a1, (kc&1)?ST1:ST0, rowB64, l7, b8, (uint32_t)kw);
        }
        __syncthreads();
        float* g = (float*)gacc;
        if (kw){
            #pragma unroll
            for (int r = 0; r < 32; r++) red[r*256 + redi] = g[r];
        }
        __syncthreads();
        if (!kw){
            #pragma unroll
            for (int r = 0; r < 32; r++) g[r] += red[r*256 + redi];
            // epilogue: enhanced = x + sigmoid(z + bg) * mr
            #pragma unroll
            for (int mt = 0; mt < 2; mt++)
                #pragma unroll
                for (int nb = 0; nb < 4; nb++){
                    int e = nc*128 + nw*32 + nb*8 + 2*(lane&3);
                    float b0 = __ldg(bg + e), b1 = __ldg(bg + e + 1);
                    #pragma unroll
                    for (int rh = 0; rh < 2; rh++){
                        int r = mw*32 + mt*16 + (lane>>2) + rh*8;
                        float z0 = gacc[mt][nb][rh*2]   + b0;
                        float z1 = gacc[mt][nb][rh*2+1] + b1;
                        uint32_t xh = *(uint32_t*)(sm + X_OFF + r*XP + 2*e);
                        uint32_t xl = *(uint32_t*)(sm + X_OFF + r*XP + XLO + 2*e);
                        uint32_t mh = *(uint32_t*)(sm + R_OFF + r*RP + 2*e);
                        uint32_t ml = *(uint32_t*)(sm + R_OFF + r*RP + RLO + 2*e);
                        float x0 = hf2sum(xh, xl, 0), x1 = hf2sum(xh, xl, 1);
                        float m0 = hf2sum(mh, ml, 0), m1 = hf2sum(mh, ml, 1);
                        float g0 = 1.f/(1.f + __expf(-z0));
                        float g1 = 1.f/(1.f + __expf(-z1));
                        *(float2*)(out_enh + (size_t)(rowbase + r)*Dq + e) =
                            make_float2(x0 + g0*m0, x1 + g1*m1);
                    }
                }
        }
        __syncthreads();   // scratch free before next pass staging
    }
}

extern "C" void kernel_launch(void* const* d_in, const int* in_sizes, int n_in,
                              void* d_out, int out_size)
{
    const float* x    = (const float*)d_in[0];
    const float* memv = (const float*)d_in[1];
    const float* wg   = (const float*)d_in[2];
    const float* bg   = (const float*)d_in[3];

    float* out_enh = (float*)d_out;
    float* out_w   = out_enh + (size_t)NROWS * Dq;

    cudaFuncSetAttribute(vm_fused, cudaFuncAttributeMaxDynamicSharedMemorySize, SMEM_BYTES);

    vm_prep<<<(Mq*Dq + 511)/512, 512>>>(memv, wg);
    vm_fused<<<NROWS/RB, NT, SMEM_BYTES>>>(x, bg, out_enh, out_w);
}

// round 15
// speedup vs baseline: 1.3900x; 1.3900x over previous
#include <cuda_runtime.h>
#include <cuda_fp16.h>
#include <stdint.h>
#include <math.h>

#define Dq 256
#define Mq 512
#define RB 64
#define NT 512
#define NROWS (32*4096)

// ---- SMEM layout ----
#define R_OFF  0
#define RP     2064
#define RLO    1040
#define X_OFF  132096
#define XP     1040
#define XLO    528
// Staging: 4 buffers x 8KB = 32KB. Group G owns buffers (G*2+0, G*2+1).
// k16 phases (B/D): hi @ +0 (4KB), lo @ +4096. Rows of 32B, chunk-XOR swizzle.
// k32 hi-only phase (E): 128 rows x 64B, chunk-XOR swizzle.
#define ST_OFF 198656
#define SMEM_BYTES 231424

__device__ __align__(16) __half g_memB_h[Mq*Dq], g_memB_l[Mq*Dq]; // [m][k]
__device__ __align__(16) __half g_memT_h[Dq*Mq], g_memT_l[Dq*Mq]; // [d][m]
__device__ __align__(16) __half g_wg_h[Dq*Mq],   g_wg_l[Dq*Mq];   // [e][dc]

__device__ __forceinline__ uint32_t smem_u32(const void* p){
    uint32_t a;
    asm("{ .reg .u64 t; cvta.to.shared.u64 t, %1; cvt.u32.u64 %0, t; }" : "=r"(a) : "l"(p));
    return a;
}
__device__ __forceinline__ void split_fp(float v, __half& h, __half& l){
    h = __float2half_rn(v);
    l = __float2half_rn(v - __half2float(h));
}
__device__ __forceinline__ uint32_t pk2(__half a, __half b){
    uint16_t ua = *(uint16_t*)&a, ub = *(uint16_t*)&b;
    return (uint32_t)ua | ((uint32_t)ub << 16);
}
__device__ __forceinline__ float hf2sum(uint32_t h, uint32_t l, int hi){
    uint16_t uh = hi ? (uint16_t)(h >> 16) : (uint16_t)h;
    uint16_t ul = hi ? (uint16_t)(l >> 16) : (uint16_t)l;
    __half bh = *(__half*)&uh, bl = *(__half*)&ul;
    return __half2float(bh) + __half2float(bl);
}
__device__ __forceinline__ void ldsm4(unsigned* a, uint32_t addr){
    asm volatile("ldmatrix.sync.aligned.m8n8.x4.shared.b16 {%0,%1,%2,%3}, [%4];"
        : "=r"(a[0]), "=r"(a[1]), "=r"(a[2]), "=r"(a[3]) : "r"(addr));
}
__device__ __forceinline__ void ldsm2(unsigned* b, uint32_t addr){
    asm volatile("ldmatrix.sync.aligned.m8n8.x2.shared.b16 {%0,%1}, [%2];"
        : "=r"(b[0]), "=r"(b[1]) : "r"(addr));
}
__device__ __forceinline__ void mma(float* d, const unsigned* a, const unsigned* b){
    asm volatile("mma.sync.aligned.m16n8k16.row.col.f32.f16.f16.f32 "
        "{%0,%1,%2,%3}, {%4,%5,%6,%7}, {%8,%9}, {%0,%1,%2,%3};"
        : "+f"(d[0]), "+f"(d[1]), "+f"(d[2]), "+f"(d[3])
        : "r"(a[0]), "r"(a[1]), "r"(a[2]), "r"(a[3]), "r"(b[0]), "r"(b[1]));
}
__device__ __forceinline__ void cpa16(uint32_t s, const void* g){
    asm volatile("cp.async.cg.shared.global [%0], [%1], 16;" :: "r"(s), "l"(g));
}
#define CP_COMMIT() asm volatile("cp.async.commit_group;" ::: "memory")
template<int N> __device__ __forceinline__ void cp_wait(){
    asm volatile("cp.async.wait_group %0;" :: "n"(N) : "memory");
}
__device__ __forceinline__ void barg(int id){
    asm volatile("bar.sync %0, 256;" :: "r"(id) : "memory");
}

// stage [128 rows][16 k] hi+lo into group's 8KB buffer (32B pitch, chunk-XOR swizzle)
__device__ __forceinline__ void stage_k16(uint32_t st, const __half* gh, const __half* gl,
        int row0, int gs, int col0){
    int t = threadIdx.x & 255;
    int row = t >> 1, c = t & 1;
    uint32_t f = (uint32_t)((row ^ (row >> 2)) & 1);
    uint32_t sa = st + row*32 + (((uint32_t)c ^ f) & 1)*16;
    size_t go = (size_t)(row0 + row)*gs + col0 + c*8;
    cpa16(sa, gh + go);
    cpa16(sa + 4096, gl + go);
}
// stage [128 rows][32 k] hi-only into group's 8KB buffer (64B pitch, chunk-XOR swizzle)
__device__ __forceinline__ void stage_k32hi(uint32_t st, const __half* gh,
        int row0, int gs, int col0){
    int t = threadIdx.x & 255;
    int row = t >> 1;
    #pragma unroll
    for (int i = 0; i < 2; i++){
        int c = (t & 1)*2 + i;
        uint32_t sa = st + row*64 + (((uint32_t)c ^ ((uint32_t)(row>>1)&3)) & 3)*16;
        cpa16(sa, gh + (size_t)(row0 + row)*gs + col0 + c*8);
    }
}

// split chunk: warp m32 x n32 x k16, 3-term => 4 ldsm4 + 8 ldsm2 + 24 mma
__device__ __forceinline__ void gemm_k16(float acc[2][4][4],
        uint32_t a0, uint32_t a1, uint32_t alo, uint32_t bBase){
    unsigned ah0[4], al0[4], ah1[4], al1[4];
    ldsm4(ah0, a0); ldsm4(al0, a0 + alo);
    ldsm4(ah1, a1); ldsm4(al1, a1 + alo);
    #pragma unroll
    for (int nb = 0; nb < 4; nb++){
        unsigned bh[2], bl[2];
        ldsm2(bh, bBase + nb*256);
        ldsm2(bl, bBase + nb*256 + 4096);
        mma(acc[0][nb], ah0, bh); mma(acc[1][nb], ah1, bh);
        mma(acc[0][nb], ah0, bl); mma(acc[1][nb], ah1, bl);
        mma(acc[0][nb], al0, bh); mma(acc[1][nb], al1, bh);
    }
}
// hi-only chunk: warp m32 x n32 x k32 => 4 ldsm4 + 8 ldsm2 + 16 mma
__device__ __forceinline__ void gemm_k32hi(float acc[2][4][4],
        uint32_t a0, uint32_t a1, uint32_t st, uint32_t bR64, uint32_t tsw, uint32_t b8){
    #pragma unroll
    for (int ki = 0; ki < 2; ki++){
        unsigned ah0[4], ah1[4];
        ldsm4(ah0, a0 + ki*32); ldsm4(ah1, a1 + ki*32);
        uint32_t sw = ((((uint32_t)ki*2 + b8) ^ tsw) & 3)*16;
        #pragma unroll
        for (int nb = 0; nb < 4; nb++){
            unsigned bh[2];
            ldsm2(bh, st + bR64 + nb*512 + sw);
            mma(acc[0][nb], ah0, bh); mma(acc[1][nb], ah1, bh);
        }
    }
}

__global__ void vm_prep(const float* __restrict__ mem, const float* __restrict__ wg){
    int idx = blockIdx.x*blockDim.x + threadIdx.x;
    if (idx < Mq*Dq){
        int m = idx >> 8, k = idx & 255;
        __half h, l;
        split_fp(mem[idx], h, l);
        g_memB_h[idx] = h;          g_memB_l[idx] = l;
        g_memT_h[k*Mq + m] = h;     g_memT_l[k*Mq + m] = l;
        split_fp(wg[idx], h, l);
        g_wg_h[idx] = h;            g_wg_l[idx] = l;
    }
}

__global__ __launch_bounds__(NT, 1)
void vm_fused(const float* __restrict__ x,
              const float* __restrict__ bg,
              float* __restrict__ out_enh,
              float* __restrict__ out_w)
{
    extern __shared__ char sm[];
    const uint32_t sm32 = smem_u32(sm);

    const int tid = threadIdx.x;
    const int wid = tid >> 5, lane = tid & 31;
    const int G  = wid >> 3;                    // group 0/1
    const int gw = wid & 7;
    const int mw = gw & 1, nw = gw >> 1;        // group warp grid 2(m) x 4(n)
    const int rowbase = blockIdx.x * RB;
    const int bid = G + 1;                      // named barrier id

    const uint32_t ST0 = sm32 + ST_OFF + (uint32_t)G*16384;
    const uint32_t ST1 = ST0 + 8192;

    const uint32_t aX0 = sm32 + X_OFF + (mw*32 + (lane&15))*XP + (lane>>4)*16;
    const uint32_t aX1 = aX0 + 16*XP;
    const uint32_t aR0 = sm32 + R_OFF + (mw*32 + (lane&15))*RP + (lane>>4)*16;
    const uint32_t aR1 = aR0 + 16*RP;

    // B-fragment lane constants
    const uint32_t l7  = (uint32_t)(lane & 7);
    const uint32_t fB  = (l7 ^ (l7 >> 2)) & 1;
    const uint32_t b8  = (uint32_t)((lane >> 3) & 1);
    const uint32_t bB16 = (uint32_t)(nw*32 + l7)*32 + ((b8 ^ fB) & 1)*16;   // k16 staging
    const uint32_t bR64 = (uint32_t)(nw*32 + l7)*64;                        // k32 staging
    const uint32_t tsw  = (l7 >> 1) & 3;

    // ---------------- Phase A: x -> split fp16 in X region -----------------
    #pragma unroll
    for (int p = 0; p < 8; p++){
        int idx = tid + p*NT;
        int r = idx >> 6, c4 = idx & 63;
        float4 v = *(const float4*)(x + (size_t)(rowbase + r)*Dq + c4*4);
        __half h0,l0,h1,l1,h2,l2,h3,l3;
        split_fp(v.x,h0,l0); split_fp(v.y,h1,l1); split_fp(v.z,h2,l2); split_fp(v.w,h3,l3);
        *(uint2*)(sm + X_OFF + r*XP + c4*8)       = make_uint2(pk2(h0,h1), pk2(h2,h3));
        *(uint2*)(sm + X_OFF + r*XP + XLO + c4*8) = make_uint2(pk2(l0,l1), pk2(l2,l3));
    }
    __syncthreads();

    // ---------------- Phase B: logits = x @ memB^T --------------------------
    // group G owns n-cols [G*256, +256), 2 passes of n128; k16 chunks.
    for (int p = 0; p < 2; p++){
        float acc[2][4][4] = {};
        int base = G*256 + p*128;
        stage_k16(ST0, g_memB_h, g_memB_l, base, Dq, 0); CP_COMMIT();
        #pragma unroll 1
        for (int kc = 0; kc < 16; kc++){
            cp_wait<0>();
            barg(bid);
            if (kc < 15){
                stage_k16(((kc+1)&1)?ST1:ST0, g_memB_h, g_memB_l, base, Dq, (kc+1)*16);
                CP_COMMIT();
            }
            gemm_k16(acc, aX0 + kc*32, aX1 + kc*32, XLO, ((kc&1)?ST1:ST0) + bB16);
        }
        #pragma unroll
        for (int mt = 0; mt < 2; mt++)
            #pragma unroll
            for (int nb = 0; nb < 4; nb++){
                int r = mw*32 + mt*16 + (lane>>2);
                int c = base + nw*32 + nb*8 + 2*(lane&3);
                *(float2*)(sm + R_OFF + r*RP + c*4)     = make_float2(acc[mt][nb][0], acc[mt][nb][1]);
                *(float2*)(sm + R_OFF + (r+8)*RP + c*4) = make_float2(acc[mt][nb][2], acc[mt][nb][3]);
            }
    }
    __syncthreads();

    // ---------------- Phase C: softmax + out_w + in-place split ------------
    for (int t4 = 0; t4 < 4; t4++){
        int r = wid*4 + t4;
        char* rbase = sm + R_OFF + r*RP;
        float v[16];
        #pragma unroll
        for (int j = 0; j < 8; j++){
            float2 pp = *(float2*)(rbase + (2*lane + 64*j)*4);
            v[2*j] = pp.x; v[2*j+1] = pp.y;
        }
        float mx = v[0];
        #pragma unroll
        for (int i = 1; i < 16; i++) mx = fmaxf(mx, v[i]);
        #pragma unroll
        for (int o = 16; o > 0; o >>= 1) mx = fmaxf(mx, __shfl_xor_sync(~0u, mx, o));
        float s = 0.f;
        #pragma unroll
        for (int i = 0; i < 16; i++){ v[i] = __expf(v[i] - mx); s += v[i]; }
        #pragma unroll
        for (int o = 16; o > 0; o >>= 1) s += __shfl_xor_sync(~0u, s, o);
        float inv = 1.f / s;
        float* wout = out_w + (size_t)(rowbase + r)*Mq;
        #pragma unroll
        for (int j = 0; j < 8; j++){
            float w0 = v[2*j]*inv, w1 = v[2*j+1]*inv;
            v[2*j] = w0; v[2*j+1] = w1;
            *(float2*)(wout + 2*lane + 64*j) = make_float2(w0, w1);
        }
        __syncwarp();
        #pragma unroll
        for (int j = 0; j < 8; j++){
            __half h0,l0,h1,l1;
            split_fp(v[2*j], h0, l0); split_fp(v[2*j+1], h1, l1);
            int c = 2*lane + 64*j;
            *(uint32_t*)(rbase + 2*c)       = pk2(h0, h1);
            *(uint32_t*)(rbase + RLO + 2*c) = pk2(l0, l1);
        }
    }
    __syncthreads();

    // ---------------- Phase D: mr = w @ memT (group n-half, k16 chunks) ----
    float dacc[2][4][4] = {};
    {
        stage_k16(ST0, g_memT_h, g_memT_l, G*128, Mq, 0); CP_COMMIT();
        #pragma unroll 1
        for (int kc = 0; kc < 32; kc++){
            cp_wait<0>();
            barg(bid);
            if (kc < 31){
                stage_k16(((kc+1)&1)?ST1:ST0, g_memT_h, g_memT_l, G*128, Mq, (kc+1)*16);
                CP_COMMIT();
            }
            gemm_k16(dacc, aR0 + kc*32, aR1 + kc*32, RLO, ((kc&1)?ST1:ST0) + bB16);
        }
    }
    __syncthreads();   // all w reads complete before overwriting R with mr
    #pragma unroll
    for (int mt = 0; mt < 2; mt++)
        #pragma unroll
        for (int nb = 0; nb < 4; nb++){
            int r = mw*32 + mt*16 + (lane>>2);
            int c = G*128 + nw*32 + nb*8 + 2*(lane&3);
            __half h0,l0,h1,l1;
            split_fp(dacc[mt][nb][0], h0, l0); split_fp(dacc[mt][nb][1], h1, l1);
            *(uint32_t*)(sm + R_OFF + r*RP + 2*c)       = pk2(h0,h1);
            *(uint32_t*)(sm + R_OFF + r*RP + RLO + 2*c) = pk2(l0,l1);
            split_fp(dacc[mt][nb][2], h0, l0); split_fp(dacc[mt][nb][3], h1, l1);
            *(uint32_t*)(sm + R_OFF + (r+8)*RP + 2*c)       = pk2(h0,h1);
            *(uint32_t*)(sm + R_OFF + (r+8)*RP + RLO + 2*c) = pk2(l0,l1);
        }
    __syncthreads();

    // ---------------- Phase E: gate = [x ; mr] @ Wg^T (hi-only, k32) -------
    {
        float gacc[2][4][4] = {};
        stage_k32hi(ST0, g_wg_h, G*128, Mq, 0); CP_COMMIT();
        #pragma unroll 1
        for (int kc = 0; kc < 16; kc++){
            cp_wait<0>();
            barg(bid);
            if (kc < 15){
                stage_k32hi(((kc+1)&1)?ST1:ST0, g_wg_h, G*128, Mq, (kc+1)*32);
                CP_COMMIT();
            }
            uint32_t a0 = (kc < 8) ? (aX0 + kc*64) : (aR0 + (kc-8)*64);
            uint32_t a1 = (kc < 8) ? (aX1 + kc*64) : (aR1 + (kc-8)*64);
            gemm_k32hi(gacc, a0, a1, (kc&1)?ST1:ST0, bR64, tsw, b8);
        }
        // epilogue: enhanced = x + sigmoid(z + bg) * mr
        #pragma unroll
        for (int mt = 0; mt < 2; mt++)
            #pragma unroll
            for (int nb = 0; nb < 4; nb++){
                int e = G*128 + nw*32 + nb*8 + 2*(lane&3);
                float b0 = __ldg(bg + e), b1 = __ldg(bg + e + 1);
                #pragma unroll
                for (int rh = 0; rh < 2; rh++){
                    int r = mw*32 + mt*16 + (lane>>2) + rh*8;
                    float z0 = gacc[mt][nb][rh*2]   + b0;
                    float z1 = gacc[mt][nb][rh*2+1] + b1;
                    uint32_t xh = *(uint32_t*)(sm + X_OFF + r*XP + 2*e);
                    uint32_t xl = *(uint32_t*)(sm + X_OFF + r*XP + XLO + 2*e);
                    uint32_t mh = *(uint32_t*)(sm + R_OFF + r*RP + 2*e);
                    uint32_t ml = *(uint32_t*)(sm + R_OFF + r*RP + RLO + 2*e);
                    float x0 = hf2sum(xh, xl, 0), x1 = hf2sum(xh, xl, 1);
                    float m0 = hf2sum(mh, ml, 0), m1 = hf2sum(mh, ml, 1);
                    float g0 = 1.f/(1.f + __expf(-z0));
                    float g1 = 1.f/(1.f + __expf(-z1));
                    *(float2*)(out_enh + (size_t)(rowbase + r)*Dq + e) =
                        make_float2(x0 + g0*m0, x1 + g1*m1);
                }
            }
    }
}

extern "C" void kernel_launch(void* const* d_in, const int* in_sizes, int n_in,
                              void* d_out, int out_size)
{
    const float* x    = (const float*)d_in[0];
    const float* memv = (const float*)d_in[1];
    const float* wg   = (const float*)d_in[2];
    const float* bg   = (const float*)d_in[3];

    float* out_enh = (float*)d_out;
    float* out_w   = out_enh + (size_t)NROWS * Dq;

    cudaFuncSetAttribute(vm_fused, cudaFuncAttributeMaxDynamicSharedMemorySize, SMEM_BYTES);

    vm_prep<<<(Mq*Dq + 511)/512, 512>>>(memv, wg);
    vm_fused<<<NROWS/RB, NT, SMEM_BYTES>>>(x, bg, out_enh, out_w);
}

// round 16
// speedup vs baseline: 1.6020x; 1.1525x over previous
#include <cuda_runtime.h>
#include <cuda_fp16.h>
#include <stdint.h>
#include <math.h>

#define Dq 256
#define Mq 512
#define RB 64
#define NT 512
#define NROWS (32*4096)

// ---- SMEM layout ----
#define R_OFF  0
#define RP     2064
#define RLO    1040
#define X_OFF  132096
#define XP     1040
#define XLO    528
// Staging: 4 buffers x 8KB = 32KB. Group G owns buffers (G*2+0, G*2+1).
// k16 phases (B): hi @ +0 (4KB), lo @ +4096. Rows of 32B, chunk-XOR swizzle.
// k32 hi-only phases (D/E): 128 rows x 64B, chunk-XOR swizzle.
#define ST_OFF 198656
#define SMEM_BYTES 231424

__device__ __align__(16) __half g_memB_h[Mq*Dq], g_memB_l[Mq*Dq]; // [m][k]
__device__ __align__(16) __half g_memT_h[Dq*Mq], g_memT_l[Dq*Mq]; // [d][m]
__device__ __align__(16) __half g_wg_h[Dq*Mq],   g_wg_l[Dq*Mq];   // [e][dc]

__device__ __forceinline__ uint32_t smem_u32(const void* p){
    uint32_t a;
    asm("{ .reg .u64 t; cvta.to.shared.u64 t, %1; cvt.u32.u64 %0, t; }" : "=r"(a) : "l"(p));
    return a;
}
__device__ __forceinline__ void split_fp(float v, __half& h, __half& l){
    h = __float2half_rn(v);
    l = __float2half_rn(v - __half2float(h));
}
__device__ __forceinline__ uint32_t pk2(__half a, __half b){
    uint16_t ua = *(uint16_t*)&a, ub = *(uint16_t*)&b;
    return (uint32_t)ua | ((uint32_t)ub << 16);
}
__device__ __forceinline__ float hf2sum(uint32_t h, uint32_t l, int hi){
    uint16_t uh = hi ? (uint16_t)(h >> 16) : (uint16_t)h;
    uint16_t ul = hi ? (uint16_t)(l >> 16) : (uint16_t)l;
    __half bh = *(__half*)&uh, bl = *(__half*)&ul;
    return __half2float(bh) + __half2float(bl);
}
__device__ __forceinline__ void ldsm4(unsigned* a, uint32_t addr){
    asm volatile("ldmatrix.sync.aligned.m8n8.x4.shared.b16 {%0,%1,%2,%3}, [%4];"
        : "=r"(a[0]), "=r"(a[1]), "=r"(a[2]), "=r"(a[3]) : "r"(addr));
}
__device__ __forceinline__ void ldsm2(unsigned* b, uint32_t addr){
    asm volatile("ldmatrix.sync.aligned.m8n8.x2.shared.b16 {%0,%1}, [%2];"
        : "=r"(b[0]), "=r"(b[1]) : "r"(addr));
}
__device__ __forceinline__ void mma(float* d, const unsigned* a, const unsigned* b){
    asm volatile("mma.sync.aligned.m16n8k16.row.col.f32.f16.f16.f32 "
        "{%0,%1,%2,%3}, {%4,%5,%6,%7}, {%8,%9}, {%0,%1,%2,%3};"
        : "+f"(d[0]), "+f"(d[1]), "+f"(d[2]), "+f"(d[3])
        : "r"(a[0]), "r"(a[1]), "r"(a[2]), "r"(a[3]), "r"(b[0]), "r"(b[1]));
}
__device__ __forceinline__ void cpa16(uint32_t s, const void* g){
    asm volatile("cp.async.cg.shared.global [%0], [%1], 16;" :: "r"(s), "l"(g));
}
#define CP_COMMIT() asm volatile("cp.async.commit_group;" ::: "memory")
template<int N> __device__ __forceinline__ void cp_wait(){
    asm volatile("cp.async.wait_group %0;" :: "n"(N) : "memory");
}
__device__ __forceinline__ void barg(int id){
    asm volatile("bar.sync %0, 256;" :: "r"(id) : "memory");
}

// stage [128 rows][16 k] hi+lo into group's 8KB buffer (32B pitch, chunk-XOR swizzle)
__device__ __forceinline__ void stage_k16(uint32_t st, const __half* gh, const __half* gl,
        int row0, int gs, int col0){
    int t = threadIdx.x & 255;
    int row = t >> 1, c = t & 1;
    uint32_t f = (uint32_t)((row ^ (row >> 2)) & 1);
    uint32_t sa = st + row*32 + (((uint32_t)c ^ f) & 1)*16;
    size_t go = (size_t)(row0 + row)*gs + col0 + c*8;
    cpa16(sa, gh + go);
    cpa16(sa + 4096, gl + go);
}
// stage [128 rows][32 k] hi-only into group's 8KB buffer (64B pitch, chunk-XOR swizzle)
__device__ __forceinline__ void stage_k32hi(uint32_t st, const __half* gh,
        int row0, int gs, int col0){
    int t = threadIdx.x & 255;
    int row = t >> 1;
    #pragma unroll
    for (int i = 0; i < 2; i++){
        int c = (t & 1)*2 + i;
        uint32_t sa = st + row*64 + (((uint32_t)c ^ ((uint32_t)(row>>1)&3)) & 3)*16;
        cpa16(sa, gh + (size_t)(row0 + row)*gs + col0 + c*8);
    }
}

// 3-term split chunk: warp m32 x n32 x k16 => 4 ldsm4 + 8 ldsm2 + 24 mma
__device__ __forceinline__ void gemm_k16(float acc[2][4][4],
        uint32_t a0, uint32_t a1, uint32_t alo, uint32_t bBase){
    unsigned ah0[4], al0[4], ah1[4], al1[4];
    ldsm4(ah0, a0); ldsm4(al0, a0 + alo);
    ldsm4(ah1, a1); ldsm4(al1, a1 + alo);
    #pragma unroll
    for (int nb = 0; nb < 4; nb++){
        unsigned bh[2], bl[2];
        ldsm2(bh, bBase + nb*256);
        ldsm2(bl, bBase + nb*256 + 4096);
        mma(acc[0][nb], ah0, bh); mma(acc[1][nb], ah1, bh);
        mma(acc[0][nb], ah0, bl); mma(acc[1][nb], ah1, bl);
        mma(acc[0][nb], al0, bh); mma(acc[1][nb], al1, bh);
    }
}
// 2-term split over k32 hi-only staging: (A_hi + A_lo)·B_hi. 8 ldsm4 + 8 ldsm2 + 32 mma
__device__ __forceinline__ void gemm_k32_2t(float acc[2][4][4],
        uint32_t a0, uint32_t a1, uint32_t alo, uint32_t st, uint32_t bR64,
        uint32_t tsw, uint32_t b8){
    #pragma unroll
    for (int ki = 0; ki < 2; ki++){
        unsigned ah0[4], ah1[4], al0[4], al1[4];
        ldsm4(ah0, a0 + ki*32); ldsm4(al0, a0 + alo + ki*32);
        ldsm4(ah1, a1 + ki*32); ldsm4(al1, a1 + alo + ki*32);
        uint32_t sw = ((((uint32_t)ki*2 + b8) ^ tsw) & 3)*16;
        #pragma unroll
        for (int nb = 0; nb < 4; nb++){
            unsigned bh[2];
            ldsm2(bh, st + bR64 + nb*512 + sw);
            mma(acc[0][nb], ah0, bh); mma(acc[1][nb], ah1, bh);
            mma(acc[0][nb], al0, bh); mma(acc[1][nb], al1, bh);
        }
    }
}
// hi-only chunk: warp m32 x n32 x k32 => 4 ldsm4 + 8 ldsm2 + 16 mma
__device__ __forceinline__ void gemm_k32hi(float acc[2][4][4],
        uint32_t a0, uint32_t a1, uint32_t st, uint32_t bR64, uint32_t tsw, uint32_t b8){
    #pragma unroll
    for (int ki = 0; ki < 2; ki++){
        unsigned ah0[4], ah1[4];
        ldsm4(ah0, a0 + ki*32); ldsm4(ah1, a1 + ki*32);
        uint32_t sw = ((((uint32_t)ki*2 + b8) ^ tsw) & 3)*16;
        #pragma unroll
        for (int nb = 0; nb < 4; nb++){
            unsigned bh[2];
            ldsm2(bh, st + bR64 + nb*512 + sw);
            mma(acc[0][nb], ah0, bh); mma(acc[1][nb], ah1, bh);
        }
    }
}

__global__ void vm_prep(const float* __restrict__ mem, const float* __restrict__ wg){
    int idx = blockIdx.x*blockDim.x + threadIdx.x;
    if (idx < Mq*Dq){
        int m = idx >> 8, k = idx & 255;
        __half h, l;
        split_fp(mem[idx], h, l);
        g_memB_h[idx] = h;          g_memB_l[idx] = l;
        g_memT_h[k*Mq + m] = h;     g_memT_l[k*Mq + m] = l;
        split_fp(wg[idx], h, l);
        g_wg_h[idx] = h;            g_wg_l[idx] = l;
    }
}

__global__ __launch_bounds__(NT, 1)
void vm_fused(const float* __restrict__ x,
              const float* __restrict__ bg,
              float* __restrict__ out_enh,
              float* __restrict__ out_w)
{
    extern __shared__ char sm[];
    const uint32_t sm32 = smem_u32(sm);

    const int tid = threadIdx.x;
    const int wid = tid >> 5, lane = tid & 31;
    const int G  = wid >> 3;                    // group 0/1
    const int gw = wid & 7;
    const int mw = gw & 1, nw = gw >> 1;        // group warp grid 2(m) x 4(n)
    const int rowbase = blockIdx.x * RB;
    const int bid = G + 1;                      // named barrier id

    const uint32_t ST0 = sm32 + ST_OFF + (uint32_t)G*16384;
    const uint32_t ST1 = ST0 + 8192;

    const uint32_t aX0 = sm32 + X_OFF + (mw*32 + (lane&15))*XP + (lane>>4)*16;
    const uint32_t aX1 = aX0 + 16*XP;
    const uint32_t aR0 = sm32 + R_OFF + (mw*32 + (lane&15))*RP + (lane>>4)*16;
    const uint32_t aR1 = aR0 + 16*RP;

    // B-fragment lane constants
    const uint32_t l7  = (uint32_t)(lane & 7);
    const uint32_t fB  = (l7 ^ (l7 >> 2)) & 1;
    const uint32_t b8  = (uint32_t)((lane >> 3) & 1);
    const uint32_t bB16 = (uint32_t)(nw*32 + l7)*32 + ((b8 ^ fB) & 1)*16;   // k16 staging
    const uint32_t bR64 = (uint32_t)(nw*32 + l7)*64;                        // k32 staging
    const uint32_t tsw  = (l7 >> 1) & 3;

    // prefetch Phase B pass-0 chunk-0 while Phase A runs
    stage_k16(ST0, g_memB_h, g_memB_l, G*256, Dq, 0); CP_COMMIT();

    // ---------------- Phase A: x -> split fp16 in X region -----------------
    #pragma unroll
    for (int p = 0; p < 8; p++){
        int idx = tid + p*NT;
        int r = idx >> 6, c4 = idx & 63;
        float4 v = *(const float4*)(x + (size_t)(rowbase + r)*Dq + c4*4);
        __half h0,l0,h1,l1,h2,l2,h3,l3;
        split_fp(v.x,h0,l0); split_fp(v.y,h1,l1); split_fp(v.z,h2,l2); split_fp(v.w,h3,l3);
        *(uint2*)(sm + X_OFF + r*XP + c4*8)       = make_uint2(pk2(h0,h1), pk2(h2,h3));
        *(uint2*)(sm + X_OFF + r*XP + XLO + c4*8) = make_uint2(pk2(l0,l1), pk2(l2,l3));
    }
    __syncthreads();

    // ---------------- Phase B: logits = x @ memB^T (3-term, k16) -----------
    for (int p = 0; p < 2; p++){
        float acc[2][4][4] = {};
        int base = G*256 + p*128;
        if (p){ stage_k16(ST0, g_memB_h, g_memB_l, base, Dq, 0); CP_COMMIT(); }
        #pragma unroll 1
        for (int kc = 0; kc < 16; kc++){
            cp_wait<0>();
            barg(bid);
            if (kc < 15){
                stage_k16(((kc+1)&1)?ST1:ST0, g_memB_h, g_memB_l, base, Dq, (kc+1)*16);
                CP_COMMIT();
            }
            gemm_k16(acc, aX0 + kc*32, aX1 + kc*32, XLO, ((kc&1)?ST1:ST0) + bB16);
        }
        #pragma unroll
        for (int mt = 0; mt < 2; mt++)
            #pragma unroll
            for (int nb = 0; nb < 4; nb++){
                int r = mw*32 + mt*16 + (lane>>2);
                int c = base + nw*32 + nb*8 + 2*(lane&3);
                *(float2*)(sm + R_OFF + r*RP + c*4)     = make_float2(acc[mt][nb][0], acc[mt][nb][1]);
                *(float2*)(sm + R_OFF + (r+8)*RP + c*4) = make_float2(acc[mt][nb][2], acc[mt][nb][3]);
            }
    }
    __syncthreads();

    // prefetch Phase D chunk-0 (memT hi, k32) while softmax runs
    stage_k32hi(ST0, g_memT_h, G*128, Mq, 0); CP_COMMIT();

    // ---------------- Phase C: softmax + out_w + in-place split ------------
    for (int t4 = 0; t4 < 4; t4++){
        int r = wid*4 + t4;
        char* rbase = sm + R_OFF + r*RP;
        float v[16];
        #pragma unroll
        for (int j = 0; j < 8; j++){
            float2 pp = *(float2*)(rbase + (2*lane + 64*j)*4);
            v[2*j] = pp.x; v[2*j+1] = pp.y;
        }
        float mx = v[0];
        #pragma unroll
        for (int i = 1; i < 16; i++) mx = fmaxf(mx, v[i]);
        #pragma unroll
        for (int o = 16; o > 0; o >>= 1) mx = fmaxf(mx, __shfl_xor_sync(~0u, mx, o));
        float s = 0.f;
        #pragma unroll
        for (int i = 0; i < 16; i++){ v[i] = __expf(v[i] - mx); s += v[i]; }
        #pragma unroll
        for (int o = 16; o > 0; o >>= 1) s += __shfl_xor_sync(~0u, s, o);
        float inv = 1.f / s;
        float* wout = out_w + (size_t)(rowbase + r)*Mq;
        #pragma unroll
        for (int j = 0; j < 8; j++){
            float w0 = v[2*j]*inv, w1 = v[2*j+1]*inv;
            v[2*j] = w0; v[2*j+1] = w1;
            *(float2*)(wout + 2*lane + 64*j) = make_float2(w0, w1);
        }
        __syncwarp();
        #pragma unroll
        for (int j = 0; j < 8; j++){
            __half h0,l0,h1,l1;
            split_fp(v[2*j], h0, l0); split_fp(v[2*j+1], h1, l1);
            int c = 2*lane + 64*j;
            *(uint32_t*)(rbase + 2*c)       = pk2(h0, h1);
            *(uint32_t*)(rbase + RLO + 2*c) = pk2(l0, l1);
        }
    }
    __syncthreads();

    // ---------------- Phase D: mr = w @ memT (2-term, k32 hi-only) ---------
    float dacc[2][4][4] = {};
    #pragma unroll 1
    for (int kc = 0; kc < 16; kc++){
        cp_wait<0>();
        barg(bid);
        if (kc < 15){
            stage_k32hi(((kc+1)&1)?ST1:ST0, g_memT_h, G*128, Mq, (kc+1)*32);
            CP_COMMIT();
        }
        gemm_k32_2t(dacc, aR0 + kc*64, aR1 + kc*64, RLO, (kc&1)?ST1:ST0, bR64, tsw, b8);
    }
    // prefetch Phase E chunk-0 (wg hi, k32) — ST0's last reader passed barrier kc=15
    stage_k32hi(ST0, g_wg_h, G*128, Mq, 0); CP_COMMIT();

    __syncthreads();   // all w reads complete before overwriting R with mr
    #pragma unroll
    for (int mt = 0; mt < 2; mt++)
        #pragma unroll
        for (int nb = 0; nb < 4; nb++){
            int r = mw*32 + mt*16 + (lane>>2);
            int c = G*128 + nw*32 + nb*8 + 2*(lane&3);
            __half h0,l0,h1,l1;
            split_fp(dacc[mt][nb][0], h0, l0); split_fp(dacc[mt][nb][1], h1, l1);
            *(uint32_t*)(sm + R_OFF + r*RP + 2*c)       = pk2(h0,h1);
            *(uint32_t*)(sm + R_OFF + r*RP + RLO + 2*c) = pk2(l0,l1);
            split_fp(dacc[mt][nb][2], h0, l0); split_fp(dacc[mt][nb][3], h1, l1);
            *(uint32_t*)(sm + R_OFF + (r+8)*RP + 2*c)       = pk2(h0,h1);
            *(uint32_t*)(sm + R_OFF + (r+8)*RP + RLO + 2*c) = pk2(l0,l1);
        }
    __syncthreads();

    // ---------------- Phase E: gate = [x ; mr] @ Wg^T (hi-only, k32) -------
    {
        float gacc[2][4][4] = {};
        #pragma unroll 1
        for (int kc = 0; kc < 16; kc++){
            cp_wait<0>();
            barg(bid);
            if (kc < 15){
                stage_k32hi(((kc+1)&1)?ST1:ST0, g_wg_h, G*128, Mq, (kc+1)*32);
                CP_COMMIT();
            }
            uint32_t a0 = (kc < 8) ? (aX0 + kc*64) : (aR0 + (kc-8)*64);
            uint32_t a1 = (kc < 8) ? (aX1 + kc*64) : (aR1 + (kc-8)*64);
            gemm_k32hi(gacc, a0, a1, (kc&1)?ST1:ST0, bR64, tsw, b8);
        }
        // epilogue: enhanced = x + sigmoid(z + bg) * mr
        #pragma unroll
        for (int mt = 0; mt < 2; mt++)
            #pragma unroll
            for (int nb = 0; nb < 4; nb++){
                int e = G*128 + nw*32 + nb*8 + 2*(lane&3);
                float b0 = __ldg(bg + e), b1 = __ldg(bg + e + 1);
                #pragma unroll
                for (int rh = 0; rh < 2; rh++){
                    int r = mw*32 + mt*16 + (lane>>2) + rh*8;
                    float z0 = gacc[mt][nb][rh*2]   + b0;
                    float z1 = gacc[mt][nb][rh*2+1] + b1;
                    uint32_t xh = *(uint32_t*)(sm + X_OFF + r*XP + 2*e);
                    uint32_t xl = *(uint32_t*)(sm + X_OFF + r*XP + XLO + 2*e);
                    uint32_t mh = *(uint32_t*)(sm + R_OFF + r*RP + 2*e);
                    uint32_t ml = *(uint32_t*)(sm + R_OFF + r*RP + RLO + 2*e);
                    float x0 = hf2sum(xh, xl, 0), x1 = hf2sum(xh, xl, 1);
                    float m0 = hf2sum(mh, ml, 0), m1 = hf2sum(mh, ml, 1);
                    float g0 = 1.f/(1.f + __expf(-z0));
                    float g1 = 1.f/(1.f + __expf(-z1));
                    *(float2*)(out_enh + (size_t)(rowbase + r)*Dq + e) =
                        make_float2(x0 + g0*m0, x1 + g1*m1);
                }
            }
    }
}

extern "C" void kernel_launch(void* const* d_in, const int* in_sizes, int n_in,
                              void* d_out, int out_size)
{
    const float* x    = (const float*)d_in[0];
    const float* memv = (const float*)d_in[1];
    const float* wg   = (const float*)d_in[2];
    const float* bg   = (const float*)d_in[3];

    float* out_enh = (float*)d_out;
    float* out_w   = out_enh + (size_t)NROWS * Dq;

    cudaFuncSetAttribute(vm_fused, cudaFuncAttributeMaxDynamicSharedMemorySize, SMEM_BYTES);

    vm_prep<<<(Mq*Dq + 511)/512, 512>>>(memv, wg);
    vm_fused<<<NROWS/RB, NT, SMEM_BYTES>>>(x, bg, out_enh, out_w);
}

// round 17
// speedup vs baseline: 1.6928x; 1.0567x over previous
#include <cuda_runtime.h>
#include <cuda_fp16.h>
#include <stdint.h>
#include <math.h>

#define Dq 256
#define Mq 512
#define RB 64
#define NT 512
#define NROWS (32*4096)

// ---- SMEM layout ----
#define R_OFF  0
#define RP     2064
#define RLO    1040
#define X_OFF  132096
#define XP     1040
#define XLO    528
// Staging: 8 pairs x 4KB = 32KB. Pair pid owns [ST_OFF + pid*4096, +4096) = 2 buffers x 2KB.
// B phase (k16 hi+lo): hi 1KB @ +0, lo @ +1024; rows 32B pitch, chunk-swap swizzle.
// D/E (k32 hi-only): 2KB; rows 64B pitch, chunk-XOR swizzle.
#define ST_OFF 198656
#define SMEM_BYTES 231424

__device__ __align__(16) __half g_memB_h[Mq*Dq], g_memB_l[Mq*Dq]; // [m][k]
__device__ __align__(16) __half g_memT_h[Dq*Mq], g_memT_l[Dq*Mq]; // [d][m]
__device__ __align__(16) __half g_wg_h[Dq*Mq],   g_wg_l[Dq*Mq];   // [e][dc]

__device__ __forceinline__ uint32_t smem_u32(const void* p){
    uint32_t a;
    asm("{ .reg .u64 t; cvta.to.shared.u64 t, %1; cvt.u32.u64 %0, t; }" : "=r"(a) : "l"(p));
    return a;
}
__device__ __forceinline__ void split_fp(float v, __half& h, __half& l){
    h = __float2half_rn(v);
    l = __float2half_rn(v - __half2float(h));
}
__device__ __forceinline__ uint32_t pk2(__half a, __half b){
    uint16_t ua = *(uint16_t*)&a, ub = *(uint16_t*)&b;
    return (uint32_t)ua | ((uint32_t)ub << 16);
}
__device__ __forceinline__ float hf2sum(uint32_t h, uint32_t l, int hi){
    uint16_t uh = hi ? (uint16_t)(h >> 16) : (uint16_t)h;
    uint16_t ul = hi ? (uint16_t)(l >> 16) : (uint16_t)l;
    __half bh = *(__half*)&uh, bl = *(__half*)&ul;
    return __half2float(bh) + __half2float(bl);
}
__device__ __forceinline__ void ldsm4(unsigned* a, uint32_t addr){
    asm volatile("ldmatrix.sync.aligned.m8n8.x4.shared.b16 {%0,%1,%2,%3}, [%4];"
        : "=r"(a[0]), "=r"(a[1]), "=r"(a[2]), "=r"(a[3]) : "r"(addr));
}
__device__ __forceinline__ void ldsm2(unsigned* b, uint32_t addr){
    asm volatile("ldmatrix.sync.aligned.m8n8.x2.shared.b16 {%0,%1}, [%2];"
        : "=r"(b[0]), "=r"(b[1]) : "r"(addr));
}
__device__ __forceinline__ void mma(float* d, const unsigned* a, const unsigned* b){
    asm volatile("mma.sync.aligned.m16n8k16.row.col.f32.f16.f16.f32 "
        "{%0,%1,%2,%3}, {%4,%5,%6,%7}, {%8,%9}, {%0,%1,%2,%3};"
        : "+f"(d[0]), "+f"(d[1]), "+f"(d[2]), "+f"(d[3])
        : "r"(a[0]), "r"(a[1]), "r"(a[2]), "r"(a[3]), "r"(b[0]), "r"(b[1]));
}
__device__ __forceinline__ void cpa16(uint32_t s, const void* g){
    asm volatile("cp.async.cg.shared.global [%0], [%1], 16;" :: "r"(s), "l"(g));
}
#define CP_COMMIT() asm volatile("cp.async.commit_group;" ::: "memory")
template<int N> __device__ __forceinline__ void cp_wait(){
    asm volatile("cp.async.wait_group %0;" :: "n"(N) : "memory");
}
__device__ __forceinline__ void barp(int id){
    asm volatile("bar.sync %0, 64;" :: "r"(id) : "memory");
}

// pair-stage [32 rows][16 k] hi+lo into 2KB buffer (32B pitch, chunk-swap swizzle)
__device__ __forceinline__ void stage_pair_k16(uint32_t dst, const __half* gh,
        const __half* gl, int row0, int gs, int col0){
    int t = threadIdx.x & 63;
    int rl = t >> 1, c = t & 1;
    uint32_t phys = ((uint32_t)c ^ ((uint32_t)(rl >> 2) & 1)) & 1;
    uint32_t sa = dst + rl*32 + phys*16;
    size_t go = (size_t)(row0 + rl)*gs + col0 + c*8;
    cpa16(sa, gh + go);
    cpa16(sa + 1024, gl + go);
}
// pair-stage [32 rows][32 k] hi-only into 2KB buffer (64B pitch, chunk-XOR swizzle)
__device__ __forceinline__ void stage_pair_k32(uint32_t dst, const __half* gh,
        int row0, int gs, int col0){
    int t = threadIdx.x & 63;
    int rl = t >> 1;
    #pragma unroll
    for (int i = 0; i < 2; i++){
        int c = (t & 1)*2 + i;
        uint32_t phys = ((uint32_t)c ^ ((uint32_t)(rl >> 1) & 3)) & 3;
        cpa16(dst + rl*64 + phys*16, gh + (size_t)(row0 + rl)*gs + col0 + c*8);
    }
}

// 3-term split chunk: warp m32 x n32 x k16 => 4 ldsm4 + 8 ldsm2 + 24 mma
// bB = pair buffer + per-lane B-fragment offset (k16 slice layout)
__device__ __forceinline__ void gemm_k16(float acc[2][4][4],
        uint32_t a0, uint32_t a1, uint32_t alo, uint32_t bB){
    unsigned ah0[4], al0[4], ah1[4], al1[4];
    ldsm4(ah0, a0); ldsm4(al0, a0 + alo);
    ldsm4(ah1, a1); ldsm4(al1, a1 + alo);
    #pragma unroll
    for (int nb = 0; nb < 4; nb++){
        unsigned bh[2], bl[2];
        ldsm2(bh, bB + nb*256);
        ldsm2(bl, bB + nb*256 + 1024);
        mma(acc[0][nb], ah0, bh); mma(acc[1][nb], ah1, bh);
        mma(acc[0][nb], ah0, bl); mma(acc[1][nb], ah1, bl);
        mma(acc[0][nb], al0, bh); mma(acc[1][nb], al1, bh);
    }
}
// 2-term split over k32 hi-only slice: (A_hi + A_lo)·B_hi => 8 ldsm4 + 8 ldsm2 + 32 mma
__device__ __forceinline__ void gemm_k32_2t(float acc[2][4][4],
        uint32_t a0, uint32_t a1, uint32_t alo, uint32_t bBase,
        uint32_t tsw, uint32_t b8){
    #pragma unroll
    for (int ki = 0; ki < 2; ki++){
        unsigned ah0[4], ah1[4], al0[4], al1[4];
        ldsm4(ah0, a0 + ki*32); ldsm4(al0, a0 + alo + ki*32);
        ldsm4(ah1, a1 + ki*32); ldsm4(al1, a1 + alo + ki*32);
        uint32_t sw = ((((uint32_t)ki*2 + b8) ^ tsw) & 3)*16;
        #pragma unroll
        for (int nb = 0; nb < 4; nb++){
            unsigned bh[2];
            ldsm2(bh, bBase + nb*512 + sw);
            mma(acc[0][nb], ah0, bh); mma(acc[1][nb], ah1, bh);
            mma(acc[0][nb], al0, bh); mma(acc[1][nb], al1, bh);
        }
    }
}
// hi-only chunk over k32 slice: 4 ldsm4 + 8 ldsm2 + 16 mma
__device__ __forceinline__ void gemm_k32hi(float acc[2][4][4],
        uint32_t a0, uint32_t a1, uint32_t bBase, uint32_t tsw, uint32_t b8){
    #pragma unroll
    for (int ki = 0; ki < 2; ki++){
        unsigned ah0[4], ah1[4];
        ldsm4(ah0, a0 + ki*32); ldsm4(ah1, a1 + ki*32);
        uint32_t sw = ((((uint32_t)ki*2 + b8) ^ tsw) & 3)*16;
        #pragma unroll
        for (int nb = 0; nb < 4; nb++){
            unsigned bh[2];
            ldsm2(bh, bBase + nb*512 + sw);
            mma(acc[0][nb], ah0, bh); mma(acc[1][nb], ah1, bh);
        }
    }
}

__global__ void vm_prep(const float* __restrict__ mem, const float* __restrict__ wg){
    int idx = blockIdx.x*blockDim.x + threadIdx.x;
    if (idx < Mq*Dq){
        int m = idx >> 8, k = idx & 255;
        __half h, l;
        split_fp(mem[idx], h, l);
        g_memB_h[idx] = h;          g_memB_l[idx] = l;
        g_memT_h[k*Mq + m] = h;     g_memT_l[k*Mq + m] = l;
        split_fp(wg[idx], h, l);
        g_wg_h[idx] = h;            g_wg_l[idx] = l;
    }
}

__global__ __launch_bounds__(NT, 1)
void vm_fused(const float* __restrict__ x,
              const float* __restrict__ bg,
              float* __restrict__ out_enh,
              float* __restrict__ out_w)
{
    extern __shared__ char sm[];
    const uint32_t sm32 = smem_u32(sm);

    const int tid = threadIdx.x;
    const int wid = tid >> 5, lane = tid & 31;
    const int G  = wid >> 3;                    // group 0/1 (n-half owner)
    const int gw = wid & 7;
    const int mw = gw & 1, nw = gw >> 1;        // warp grid 2(m) x 4(n) per group
    const int pid = G*4 + nw;                   // pair id 0..7 (m-pair shares B slice)
    const int pb  = 1 + pid;                    // named barrier id (64 threads)
    const int rowbase = blockIdx.x * RB;

    const uint32_t PST0 = sm32 + ST_OFF + (uint32_t)pid*4096;
    const uint32_t PST1 = PST0 + 2048;

    const uint32_t aX0 = sm32 + X_OFF + (mw*32 + (lane&15))*XP + (lane>>4)*16;
    const uint32_t aX1 = aX0 + 16*XP;
    const uint32_t aR0 = sm32 + R_OFF + (mw*32 + (lane&15))*RP + (lane>>4)*16;
    const uint32_t aR1 = aR0 + 16*RP;

    // B-fragment lane constants (slice-local)
    const uint32_t l7  = (uint32_t)(lane & 7);
    const uint32_t b8  = (uint32_t)((lane >> 3) & 1);
    const uint32_t bB16 = l7*32 + ((b8 ^ ((l7 >> 2) & 1)) & 1)*16;  // k16 slice
    const uint32_t bR64 = l7*64;                                     // k32 slice row base
    const uint32_t tsw  = (l7 >> 1) & 3;

    // prefetch Phase B chunk 0 (pair slice) while Phase A runs
    stage_pair_k16(PST0, g_memB_h, g_memB_l, G*256 + nw*32, Dq, 0); CP_COMMIT();

    // ---------------- Phase A: x -> split fp16 in X region -----------------
    #pragma unroll
    for (int p = 0; p < 8; p++){
        int idx = tid + p*NT;
        int r = idx >> 6, c4 = idx & 63;
        float4 v = *(const float4*)(x + (size_t)(rowbase + r)*Dq + c4*4);
        __half h0,l0,h1,l1,h2,l2,h3,l3;
        split_fp(v.x,h0,l0); split_fp(v.y,h1,l1); split_fp(v.z,h2,l2); split_fp(v.w,h3,l3);
        *(uint2*)(sm + X_OFF + r*XP + c4*8)       = make_uint2(pk2(h0,h1), pk2(h2,h3));
        *(uint2*)(sm + X_OFF + r*XP + XLO + c4*8) = make_uint2(pk2(l0,l1), pk2(l2,l3));
    }
    __syncthreads();

    // ---------------- Phase B: logits = x @ memB^T (3-term, k16, 32 chunks) -
    {
        float acc[2][4][4] = {};
        #pragma unroll 1
        for (int cc = 0; cc < 32; cc++){
            cp_wait<0>();
            barp(pb);
            if (cc < 31){
                int nx = cc + 1;
                stage_pair_k16((nx&1)?PST1:PST0, g_memB_h, g_memB_l,
                               G*256 + (nx>>4)*128 + nw*32, Dq, (nx&15)*16);
                CP_COMMIT();
            }
            int kcl = cc & 15;
            gemm_k16(acc, aX0 + kcl*32, aX1 + kcl*32, XLO, ((cc&1)?PST1:PST0) + bB16);
            if (kcl == 15){
                int base = G*256 + (cc>>4)*128;
                #pragma unroll
                for (int mt = 0; mt < 2; mt++)
                    #pragma unroll
                    for (int nb = 0; nb < 4; nb++){
                        int r = mw*32 + mt*16 + (lane>>2);
                        int c = base + nw*32 + nb*8 + 2*(lane&3);
                        *(float2*)(sm + R_OFF + r*RP + c*4)     = make_float2(acc[mt][nb][0], acc[mt][nb][1]);
                        *(float2*)(sm + R_OFF + (r+8)*RP + c*4) = make_float2(acc[mt][nb][2], acc[mt][nb][3]);
                        acc[mt][nb][0]=0.f; acc[mt][nb][1]=0.f; acc[mt][nb][2]=0.f; acc[mt][nb][3]=0.f;
                    }
            }
        }
    }
    __syncthreads();

    // prefetch Phase D chunk-0 (memT hi, k32 pair slice) while softmax runs
    stage_pair_k32(PST0, g_memT_h, G*128 + nw*32, Mq, 0); CP_COMMIT();

    // ---------------- Phase C: softmax + out_w + in-place split ------------
    for (int t4 = 0; t4 < 4; t4++){
        int r = wid*4 + t4;
        char* rbase = sm + R_OFF + r*RP;
        float v[16];
        #pragma unroll
        for (int j = 0; j < 8; j++){
            float2 pp = *(float2*)(rbase + (2*lane + 64*j)*4);
            v[2*j] = pp.x; v[2*j+1] = pp.y;
        }
        float mx = v[0];
        #pragma unroll
        for (int i = 1; i < 16; i++) mx = fmaxf(mx, v[i]);
        #pragma unroll
        for (int o = 16; o > 0; o >>= 1) mx = fmaxf(mx, __shfl_xor_sync(~0u, mx, o));
        float s = 0.f;
        #pragma unroll
        for (int i = 0; i < 16; i++){ v[i] = __expf(v[i] - mx); s += v[i]; }
        #pragma unroll
        for (int o = 16; o > 0; o >>= 1) s += __shfl_xor_sync(~0u, s, o);
        float inv = 1.f / s;
        float* wout = out_w + (size_t)(rowbase + r)*Mq;
        #pragma unroll
        for (int j = 0; j < 8; j++){
            float w0 = v[2*j]*inv, w1 = v[2*j+1]*inv;
            v[2*j] = w0; v[2*j+1] = w1;
            *(float2*)(wout + 2*lane + 64*j) = make_float2(w0, w1);
        }
        __syncwarp();
        #pragma unroll
        for (int j = 0; j < 8; j++){
            __half h0,l0,h1,l1;
            split_fp(v[2*j], h0, l0); split_fp(v[2*j+1], h1, l1);
            int c = 2*lane + 64*j;
            *(uint32_t*)(rbase + 2*c)       = pk2(h0, h1);
            *(uint32_t*)(rbase + RLO + 2*c) = pk2(l0, l1);
        }
    }
    __syncthreads();

    // ---------------- Phase D: mr = w @ memT (2-term, k32 hi-only) ---------
    float dacc[2][4][4] = {};
    #pragma unroll 1
    for (int kc = 0; kc < 16; kc++){
        cp_wait<0>();
        barp(pb);
        if (kc < 15){
            stage_pair_k32(((kc+1)&1)?PST1:PST0, g_memT_h, G*128 + nw*32, Mq, (kc+1)*32);
            CP_COMMIT();
        }
        gemm_k32_2t(dacc, aR0 + kc*64, aR1 + kc*64, RLO,
                    (((kc&1)?PST1:PST0)) + bR64, tsw, b8);
    }
    // prefetch Phase E chunk-0 — buf0's last reader (chunk 14) passed barrier kc=15
    stage_pair_k32(PST0, g_wg_h, G*128 + nw*32, Mq, 0); CP_COMMIT();

    __syncthreads();   // all w reads complete before overwriting R with mr
    #pragma unroll
    for (int mt = 0; mt < 2; mt++)
        #pragma unroll
        for (int nb = 0; nb < 4; nb++){
            int r = mw*32 + mt*16 + (lane>>2);
            int c = G*128 + nw*32 + nb*8 + 2*(lane&3);
            __half h0,l0,h1,l1;
            split_fp(dacc[mt][nb][0], h0, l0); split_fp(dacc[mt][nb][1], h1, l1);
            *(uint32_t*)(sm + R_OFF + r*RP + 2*c)       = pk2(h0,h1);
            *(uint32_t*)(sm + R_OFF + r*RP + RLO + 2*c) = pk2(l0,l1);
            split_fp(dacc[mt][nb][2], h0, l0); split_fp(dacc[mt][nb][3], h1, l1);
            *(uint32_t*)(sm + R_OFF + (r+8)*RP + 2*c)       = pk2(h0,h1);
            *(uint32_t*)(sm + R_OFF + (r+8)*RP + RLO + 2*c) = pk2(l0,l1);
        }
    __syncthreads();

    // ---------------- Phase E: gate = [x ; mr] @ Wg^T (hi-only, k32) -------
    {
        float gacc[2][4][4] = {};
        #pragma unroll 1
        for (int kc = 0; kc < 16; kc++){
            cp_wait<0>();
            barp(pb);
            if (kc < 15){
                stage_pair_k32(((kc+1)&1)?PST1:PST0, g_wg_h, G*128 + nw*32, Mq, (kc+1)*32);
                CP_COMMIT();
            }
            uint32_t a0 = (kc < 8) ? (aX0 + kc*64) : (aR0 + (kc-8)*64);
            uint32_t a1 = (kc < 8) ? (aX1 + kc*64) : (aR1 + (kc-8)*64);
            gemm_k32hi(gacc, a0, a1, (((kc&1)?PST1:PST0)) + bR64, tsw, b8);
        }
        // epilogue: enhanced = x + sigmoid(z + bg) * mr
        #pragma unroll
        for (int mt = 0; mt < 2; mt++)
            #pragma unroll
            for (int nb = 0; nb < 4; nb++){
                int e = G*128 + nw*32 + nb*8 + 2*(lane&3);
                float b0 = __ldg(bg + e), b1 = __ldg(bg + e + 1);
                #pragma unroll
                for (int rh = 0; rh < 2; rh++){
                    int r = mw*32 + mt*16 + (lane>>2) + rh*8;
                    float z0 = gacc[mt][nb][rh*2]   + b0;
                    float z1 = gacc[mt][nb][rh*2+1] + b1;
                    uint32_t xh = *(uint32_t*)(sm + X_OFF + r*XP + 2*e);
                    uint32_t xl = *(uint32_t*)(sm + X_OFF + r*XP + XLO + 2*e);
                    uint32_t mh = *(uint32_t*)(sm + R_OFF + r*RP + 2*e);
                    uint32_t ml = *(uint32_t*)(sm + R_OFF + r*RP + RLO + 2*e);
                    float x0 = hf2sum(xh, xl, 0), x1 = hf2sum(xh, xl, 1);
                    float m0 = hf2sum(mh, ml, 0), m1 = hf2sum(mh, ml, 1);
                    float g0 = 1.f/(1.f + __expf(-z0));
                    float g1 = 1.f/(1.f + __expf(-z1));
                    *(float2*)(out_enh + (size_t)(rowbase + r)*Dq + e) =
                        make_float2(x0 + g0*m0, x1 + g1*m1);
                }
            }
    }
}

extern "C" void kernel_launch(void* const* d_in, const int* in_sizes, int n_in,
                              void* d_out, int out_size)
{
    const float* x    = (const float*)d_in[0];
    const float* memv = (const float*)d_in[1];
    const float* wg   = (const float*)d_in[2];
    const float* bg   = (const float*)d_in[3];

    float* out_enh = (float*)d_out;
    float* out_w   = out_enh + (size_t)NROWS * Dq;

    cudaFuncSetAttribute(vm_fused, cudaFuncAttributeMaxDynamicSharedMemorySize, SMEM_BYTES);

    vm_prep<<<(Mq*Dq + 511)/512, 512>>>(memv, wg);
    vm_fused<<<NROWS/RB, NT, SMEM_BYTES>>>(x, bg, out_enh, out_w);
}